// round 1
// baseline (speedup 1.0000x reference)
#include <cuda_runtime.h>
#include <cstdint>

#define HNUM 12
#define NTOK 2048
#define DMODEL 768
#define PD 64
#define BATCH 2

// scratch (device globals — no allocations allowed)
static __device__ float g_Q[BATCH * HNUM * NTOK * PD];
static __device__ float g_K[BATCH * HNUM * NTOK * PD];
static __device__ float g_V[BATCH * HNUM * NTOK * PD];

__device__ __forceinline__ uint32_t f2tf(float x) {
    uint32_t u;
    asm("cvt.rna.tf32.f32 %0, %1;" : "=r"(u) : "f"(x));
    return u;
}

__device__ __forceinline__ void mma8(float c[4], uint32_t a0, uint32_t a1, uint32_t a2, uint32_t a3,
                                     uint32_t b0, uint32_t b1) {
    asm volatile(
        "mma.sync.aligned.m16n8k8.row.col.f32.tf32.tf32.f32 "
        "{%0,%1,%2,%3},{%4,%5,%6,%7},{%8,%9},{%0,%1,%2,%3};\n"
        : "+f"(c[0]), "+f"(c[1]), "+f"(c[2]), "+f"(c[3])
        : "r"(a0), "r"(a1), "r"(a2), "r"(a3), "r"(b0), "r"(b1));
}

// C[m,n] = sum_k X[m,k] * W[n,k] + bias[n], 3xTF32 for fp32-quality.
// mode 0: all n -> g_Q ; mode 1: n<768 -> g_K, else g_V (n-768).
// Scatter layout: (b, h, itok, d) with b=m>>11, itok=m&2047, h=n/64, d=n%64.
__global__ __launch_bounds__(128) void proj_kernel(const float* __restrict__ X,
                                                   const float* __restrict__ W,
                                                   const float* __restrict__ bias,
                                                   int mode) {
    __shared__ float Xs[64][36];
    __shared__ float Ws[64][36];
    const int tid = threadIdx.x;
    const int w = tid >> 5;
    const int lane = tid & 31;
    const int r0 = lane >> 2;   // mma row group
    const int q4 = lane & 3;    // mma k/col group
    const int m0 = blockIdx.x * 64;
    const int n0 = blockIdx.y * 64;

    float acc[8][4];
#pragma unroll
    for (int i = 0; i < 8; ++i) {
        acc[i][0] = 0.f; acc[i][1] = 0.f; acc[i][2] = 0.f; acc[i][3] = 0.f;
    }

    for (int kc = 0; kc < DMODEL; kc += 32) {
        __syncthreads();
#pragma unroll
        for (int it = 0; it < 4; ++it) {
            int idx4 = tid + it * 128;
            int r = idx4 >> 3;
            int c4 = (idx4 & 7) * 4;
            *reinterpret_cast<float4*>(&Xs[r][c4]) =
                *reinterpret_cast<const float4*>(&X[(m0 + r) * DMODEL + kc + c4]);
            *reinterpret_cast<float4*>(&Ws[r][c4]) =
                *reinterpret_cast<const float4*>(&W[(n0 + r) * DMODEL + kc + c4]);
        }
        __syncthreads();
#pragma unroll
        for (int kk = 0; kk < 4; ++kk) {
            const int k0 = kk * 8 + q4;
            float a0f = Xs[w * 16 + r0][k0];
            float a1f = Xs[w * 16 + r0 + 8][k0];
            float a2f = Xs[w * 16 + r0][k0 + 4];
            float a3f = Xs[w * 16 + r0 + 8][k0 + 4];
            uint32_t ah0 = f2tf(a0f), ah1 = f2tf(a1f), ah2 = f2tf(a2f), ah3 = f2tf(a3f);
            uint32_t al0 = f2tf(a0f - __uint_as_float(ah0));
            uint32_t al1 = f2tf(a1f - __uint_as_float(ah1));
            uint32_t al2 = f2tf(a2f - __uint_as_float(ah2));
            uint32_t al3 = f2tf(a3f - __uint_as_float(ah3));
#pragma unroll
            for (int nt = 0; nt < 8; ++nt) {
                float b0f = Ws[nt * 8 + r0][k0];
                float b1f = Ws[nt * 8 + r0][k0 + 4];
                uint32_t bh0 = f2tf(b0f), bh1 = f2tf(b1f);
                uint32_t bl0 = f2tf(b0f - __uint_as_float(bh0));
                uint32_t bl1 = f2tf(b1f - __uint_as_float(bh1));
                mma8(acc[nt], al0, al1, al2, al3, bh0, bh1);
                mma8(acc[nt], ah0, ah1, ah2, ah3, bl0, bl1);
                mma8(acc[nt], ah0, ah1, ah2, ah3, bh0, bh1);
            }
        }
    }

    const int c0 = q4 * 2;
#pragma unroll
    for (int nt = 0; nt < 8; ++nt) {
        int n = n0 + nt * 8 + c0;
        float bias0 = bias[n];
        float bias1 = bias[n + 1];
#pragma unroll
        for (int half = 0; half < 2; ++half) {
            int m = m0 + (w << 4) + r0 + half * 8;
            int btk = m >> 11;
            int itok = m & (NTOK - 1);
            float v0 = acc[nt][half * 2 + 0] + bias0;
            float v1 = acc[nt][half * 2 + 1] + bias1;
            float* dst;
            int nn = n;
            if (mode == 0) {
                dst = g_Q;
            } else if (n < DMODEL) {
                dst = g_K;
            } else {
                dst = g_V;
                nn = n - DMODEL;
            }
            int hh = nn >> 6;
            int dd = nn & 63;
            *reinterpret_cast<float2*>(
                &dst[(((btk * HNUM + hh) * NTOK + itok) << 6) + dd]) = make_float2(v0, v1);
        }
    }
}

// Flash attention, fp32 I/O. One block = one (b, h, 64-query tile).
// 4 warps * 16 query rows each. Keys streamed in chunks of 64.
// S = Q K^T in 3xTF32, online softmax in registers, O += P V in 1xTF32.
#define SSTRIDE 68
__global__ __launch_bounds__(128) void attn_kernel(float* __restrict__ out) {
    extern __shared__ float sm[];
    float* Qs = sm;                    // 64 x 68
    float* Ks = sm + 64 * SSTRIDE;     // 64 x 68
    float* Vs = sm + 2 * 64 * SSTRIDE; // 64 x 68
    float* Ps = sm + 3 * 64 * SSTRIDE; // 64 x 68

    const int tid = threadIdx.x;
    const int w = tid >> 5;
    const int lane = tid & 31;
    const int r0 = lane >> 2;
    const int q4 = lane & 3;
    const int b = blockIdx.z;
    const int h = blockIdx.y;
    const int i0 = blockIdx.x * 64;

    const int base = ((b * HNUM + h) * NTOK) * PD;
    const float* Qg = g_Q + base;
    const float* Kg = g_K + base;
    const float* Vg = g_V + base;
    float* Og = out + base;

    // stage Q tile (64 x 64) into smem, coalesced
#pragma unroll
    for (int it = 0; it < 8; ++it) {
        int idx4 = tid + it * 128;
        int r = idx4 >> 4;
        int c4 = (idx4 & 15) * 4;
        *reinterpret_cast<float4*>(&Qs[r * SSTRIDE + c4]) =
            *reinterpret_cast<const float4*>(&Qg[(i0 + r) * PD + c4]);
    }

    float m0r = -1e30f, m1r = -1e30f, l0 = 0.f, l1 = 0.f;
    float Oacc[8][4];
#pragma unroll
    for (int i = 0; i < 8; ++i) {
        Oacc[i][0] = 0.f; Oacc[i][1] = 0.f; Oacc[i][2] = 0.f; Oacc[i][3] = 0.f;
    }

    for (int j0 = 0; j0 < NTOK; j0 += 64) {
        __syncthreads();
#pragma unroll
        for (int it = 0; it < 8; ++it) {
            int idx4 = tid + it * 128;
            int r = idx4 >> 4;
            int c4 = (idx4 & 15) * 4;
            *reinterpret_cast<float4*>(&Ks[r * SSTRIDE + c4]) =
                *reinterpret_cast<const float4*>(&Kg[(j0 + r) * PD + c4]);
            *reinterpret_cast<float4*>(&Vs[r * SSTRIDE + c4]) =
                *reinterpret_cast<const float4*>(&Vg[(j0 + r) * PD + c4]);
        }
        __syncthreads();

        // ---- S = Q K^T (3xTF32) ----
        float s[8][4];
#pragma unroll
        for (int i = 0; i < 8; ++i) {
            s[i][0] = 0.f; s[i][1] = 0.f; s[i][2] = 0.f; s[i][3] = 0.f;
        }
#pragma unroll
        for (int kk = 0; kk < 8; ++kk) {
            const int k0 = kk * 8 + q4;
            const float* qrowA = &Qs[(w * 16 + r0) * SSTRIDE];
            const float* qrowB = &Qs[(w * 16 + r0 + 8) * SSTRIDE];
            float a0f = qrowA[k0];
            float a1f = qrowB[k0];
            float a2f = qrowA[k0 + 4];
            float a3f = qrowB[k0 + 4];
            uint32_t ah0 = f2tf(a0f), ah1 = f2tf(a1f), ah2 = f2tf(a2f), ah3 = f2tf(a3f);
            uint32_t al0 = f2tf(a0f - __uint_as_float(ah0));
            uint32_t al1 = f2tf(a1f - __uint_as_float(ah1));
            uint32_t al2 = f2tf(a2f - __uint_as_float(ah2));
            uint32_t al3 = f2tf(a3f - __uint_as_float(ah3));
#pragma unroll
            for (int nt = 0; nt < 8; ++nt) {
                float b0f = Ks[(nt * 8 + r0) * SSTRIDE + k0];
                float b1f = Ks[(nt * 8 + r0) * SSTRIDE + k0 + 4];
                uint32_t bh0 = f2tf(b0f), bh1 = f2tf(b1f);
                uint32_t bl0 = f2tf(b0f - __uint_as_float(bh0));
                uint32_t bl1 = f2tf(b1f - __uint_as_float(bh1));
                mma8(s[nt], al0, al1, al2, al3, bh0, bh1);
                mma8(s[nt], ah0, ah1, ah2, ah3, bl0, bl1);
                mma8(s[nt], ah0, ah1, ah2, ah3, bh0, bh1);
            }
        }

        // ---- online softmax update ----
        float cm0 = -1e30f, cm1 = -1e30f;
#pragma unroll
        for (int nt = 0; nt < 8; ++nt) {
            cm0 = fmaxf(cm0, fmaxf(s[nt][0], s[nt][1]));
            cm1 = fmaxf(cm1, fmaxf(s[nt][2], s[nt][3]));
        }
        cm0 = fmaxf(cm0, __shfl_xor_sync(0xffffffffu, cm0, 1));
        cm0 = fmaxf(cm0, __shfl_xor_sync(0xffffffffu, cm0, 2));
        cm1 = fmaxf(cm1, __shfl_xor_sync(0xffffffffu, cm1, 1));
        cm1 = fmaxf(cm1, __shfl_xor_sync(0xffffffffu, cm1, 2));
        float nm0 = fmaxf(m0r, cm0);
        float nm1 = fmaxf(m1r, cm1);
        float sc0 = __expf(m0r - nm0);
        float sc1 = __expf(m1r - nm1);
        m0r = nm0;
        m1r = nm1;

        float ps0 = 0.f, ps1 = 0.f;
#pragma unroll
        for (int nt = 0; nt < 8; ++nt) {
            s[nt][0] = __expf(s[nt][0] - nm0);
            s[nt][1] = __expf(s[nt][1] - nm0);
            s[nt][2] = __expf(s[nt][2] - nm1);
            s[nt][3] = __expf(s[nt][3] - nm1);
            ps0 += s[nt][0] + s[nt][1];
            ps1 += s[nt][2] + s[nt][3];
        }
        ps0 += __shfl_xor_sync(0xffffffffu, ps0, 1);
        ps0 += __shfl_xor_sync(0xffffffffu, ps0, 2);
        ps1 += __shfl_xor_sync(0xffffffffu, ps1, 1);
        ps1 += __shfl_xor_sync(0xffffffffu, ps1, 2);
        l0 = l0 * sc0 + ps0;
        l1 = l1 * sc1 + ps1;

#pragma unroll
        for (int dt = 0; dt < 8; ++dt) {
            Oacc[dt][0] *= sc0; Oacc[dt][1] *= sc0;
            Oacc[dt][2] *= sc1; Oacc[dt][3] *= sc1;
        }

        // ---- P -> smem (re-fragment for A operand) ----
#pragma unroll
        for (int nt = 0; nt < 8; ++nt) {
            *reinterpret_cast<float2*>(&Ps[(w * 16 + r0) * SSTRIDE + nt * 8 + 2 * q4]) =
                make_float2(s[nt][0], s[nt][1]);
            *reinterpret_cast<float2*>(&Ps[(w * 16 + r0 + 8) * SSTRIDE + nt * 8 + 2 * q4]) =
                make_float2(s[nt][2], s[nt][3]);
        }
        __syncwarp();

        // ---- O += P V (1xTF32; P in [0,1], error ~4e-4 OK) ----
#pragma unroll
        for (int kk = 0; kk < 8; ++kk) {
            const int kcol = kk * 8 + q4;
            uint32_t a0 = f2tf(Ps[(w * 16 + r0) * SSTRIDE + kcol]);
            uint32_t a1 = f2tf(Ps[(w * 16 + r0 + 8) * SSTRIDE + kcol]);
            uint32_t a2 = f2tf(Ps[(w * 16 + r0) * SSTRIDE + kcol + 4]);
            uint32_t a3 = f2tf(Ps[(w * 16 + r0 + 8) * SSTRIDE + kcol + 4]);
#pragma unroll
            for (int dt = 0; dt < 8; ++dt) {
                uint32_t b0 = f2tf(Vs[(kk * 8 + q4) * SSTRIDE + dt * 8 + r0]);
                uint32_t b1 = f2tf(Vs[(kk * 8 + q4 + 4) * SSTRIDE + dt * 8 + r0]);
                mma8(Oacc[dt], a0, a1, a2, a3, b0, b1);
            }
        }
    }

    // ---- epilogue: normalize and write (out layout == (b,h,i,d) flat) ----
    float inv0 = 1.0f / l0;
    float inv1 = 1.0f / l1;
    const int orow = i0 + w * 16 + r0;
#pragma unroll
    for (int dt = 0; dt < 8; ++dt) {
        *reinterpret_cast<float2*>(&Og[orow * PD + dt * 8 + 2 * q4]) =
            make_float2(Oacc[dt][0] * inv0, Oacc[dt][1] * inv0);
        *reinterpret_cast<float2*>(&Og[(orow + 8) * PD + dt * 8 + 2 * q4]) =
            make_float2(Oacc[dt][2] * inv1, Oacc[dt][3] * inv1);
    }
}

extern "C" void kernel_launch(void* const* d_in, const int* in_sizes, int n_in,
                              void* d_out, int out_size) {
    (void)in_sizes; (void)n_in; (void)out_size;
    const float* x1 = (const float*)d_in[0];
    const float* x2 = (const float*)d_in[1];
    const float* Wq = (const float*)d_in[2];
    const float* bq = (const float*)d_in[3];
    const float* Wkv = (const float*)d_in[4];
    const float* bkv = (const float*)d_in[5];
    float* out = (float*)d_out;

    // Q = x2 @ Wq^T + bq
    proj_kernel<<<dim3(64, 12), 128>>>(x2, Wq, bq, 0);
    // K,V = x1 @ Wkv^T + bkv
    proj_kernel<<<dim3(64, 24), 128>>>(x1, Wkv, bkv, 1);

    const int smem_bytes = 4 * 64 * SSTRIDE * sizeof(float); // 69632
    cudaFuncSetAttribute(attn_kernel, cudaFuncAttributeMaxDynamicSharedMemorySize, smem_bytes);
    attn_kernel<<<dim3(NTOK / 64, HNUM, BATCH), 128, smem_bytes>>>(out);
}